// round 16
// baseline (speedup 1.0000x reference)
#include <cuda_runtime.h>
#include <cuda_fp16.h>
#include <math.h>

// ---------------------------------------------------------------------------
// GNN_11957188952096: pre-linear -> SAGE(32->64) -> SAGE(64->64) -> pool -> MLP
// N=100000 nodes, E=1600000 edges, G=512 graphs
// CSR gather (fp16) + tensor-core (mma.sync) combine fused per conv.
// ---------------------------------------------------------------------------

#define MAXN 100000
#define MAXE 1600000
#define MAXG 512
#define SCAN_B 1024
#define AFLAG (1u << 30)
#define PFLAG (2u << 30)

__device__ __half2 g_h0h[MAXN * 16];   // pre-linear output (fp16), 32 feats
__device__ __half2 g_h1h[MAXN * 32];   // conv1 output (fp16), 64 feats
__device__ __align__(16) __half g_w1h[64 * 64];    // [c1_wl; c1_wr] fp16
__device__ __align__(16) __half g_w2h[128 * 64];   // [c2_wl; c2_wr] fp16
__device__ float g_gsum[MAXG * 64];
__device__ float g_gcnt[MAXG];

__device__ int g_deg[MAXN];
__device__ int g_rowptr[MAXN];
__device__ int g_fill[MAXN];
__device__ int g_adj[MAXE];
__device__ unsigned g_state[128];

__device__ __forceinline__ void red_add_f32(float* addr, float v) {
    asm volatile("red.global.add.f32 [%0], %1;" :: "l"(addr), "f"(v) : "memory");
}
__device__ __forceinline__ void acc_u4(float* acc, uint4 v) {
    float2 f;
    f = __half22float2(*(__half2*)&v.x);            acc[0] += f.x; acc[1] += f.y;
    f = __half22float2(*(((__half2*)&v.x) + 1));    acc[2] += f.x; acc[3] += f.y;
    f = __half22float2(*(__half2*)&v.z);            acc[4] += f.x; acc[5] += f.y;
    f = __half22float2(*(((__half2*)&v.z) + 1));    acc[6] += f.x; acc[7] += f.y;
}
__device__ __forceinline__ uint4 pack8h(const float* a, float s) {
    uint4 o;
    *(__half2*)&o.x = __floats2half2_rn(a[0] * s, a[1] * s);
    *(((__half2*)&o.x) + 1) = __floats2half2_rn(a[2] * s, a[3] * s);
    *(__half2*)&o.z = __floats2half2_rn(a[4] * s, a[5] * s);
    *(((__half2*)&o.z) + 1) = __floats2half2_rn(a[6] * s, a[7] * s);
    return o;
}

#define LDSM_X4(r0, r1, r2, r3, a) \
    asm volatile("ldmatrix.sync.aligned.m8n8.x4.shared.b16 {%0,%1,%2,%3},[%4];" \
                 : "=r"(r0), "=r"(r1), "=r"(r2), "=r"(r3) : "r"(a))
#define LDSM_X4T(r0, r1, r2, r3, a) \
    asm volatile("ldmatrix.sync.aligned.m8n8.x4.trans.shared.b16 {%0,%1,%2,%3},[%4];" \
                 : "=r"(r0), "=r"(r1), "=r"(r2), "=r"(r3) : "r"(a))
#define MMA16816(c, a0, a1, a2, a3, b0, b1) \
    asm volatile("mma.sync.aligned.m16n8k16.row.col.f32.f16.f16.f32 " \
                 "{%0,%1,%2,%3},{%4,%5,%6,%7},{%8,%9},{%0,%1,%2,%3};" \
                 : "+f"(c[0]), "+f"(c[1]), "+f"(c[2]), "+f"(c[3]) \
                 : "r"(a0), "r"(a1), "r"(a2), "r"(a3), "r"(b0), "r"(b1))

// ---------------------------------------------------------------------------
__global__ void zero_small(int N) {
    int i = blockIdx.x * blockDim.x + threadIdx.x;
    int stride = gridDim.x * blockDim.x;
    for (int k = i; k < N; k += stride) g_deg[k] = 0;
    for (int k = i; k < MAXG * 64; k += stride) g_gsum[k] = 0.f;
    for (int k = i; k < MAXG; k += stride) g_gcnt[k] = 0.f;
    if (i < 128) g_state[i] = 0u;
}

__global__ void hist_kernel(const int* __restrict__ dst, int E) {
    int e = blockIdx.x * blockDim.x + threadIdx.x;
    if (e < E) atomicAdd(&g_deg[dst[e]], 1);
}

// exclusive scan via decoupled lookback; also fill = rowptr
__global__ void scan_kernel(int N) {
    __shared__ int buf0[SCAN_B], buf1[SCAN_B];
    __shared__ int s_run;
    int t = threadIdx.x, bid = blockIdx.x;
    int g = bid * SCAN_B + t;
    int v = (g < N) ? g_deg[g] : 0;
    buf0[t] = v;
    int* a = buf0; int* b = buf1;
#pragma unroll
    for (int off = 1; off < SCAN_B; off <<= 1) {
        __syncthreads();
        b[t] = (t >= off) ? a[t] + a[t - off] : a[t];
        int* tmp = a; a = b; b = tmp;
    }
    __syncthreads();
    int incl = a[t];
    int bsum = a[SCAN_B - 1];
    if (t == 0) {
        if (bid == 0) {
            atomicExch(&g_state[0], PFLAG | (unsigned)bsum);
            s_run = 0;
        } else {
            atomicExch(&g_state[bid], AFLAG | (unsigned)bsum);
            int run = 0;
            for (int j = bid - 1; j >= 0; j--) {
                unsigned s;
                do { s = atomicAdd(&g_state[j], 0u); } while ((s >> 30) == 0);
                run += (int)(s & 0x3FFFFFFFu);
                if (s & PFLAG) break;
            }
            atomicExch(&g_state[bid], PFLAG | (unsigned)(run + bsum));
            s_run = run;
        }
    }
    __syncthreads();
    if (g < N) {
        int r = incl - v + s_run;
        g_rowptr[g] = r;
        g_fill[g] = r;
    }
}

// placement: fill pre-initialized to rowptr -> single atomic per edge (2/thread)
__global__ void place_kernel(const int* __restrict__ src, const int* __restrict__ dst,
                             int E) {
    int i = blockIdx.x * blockDim.x + threadIdx.x;
    int E2 = E >> 1;
    if (i < E2) {
        int2 d2 = __ldg(&((const int2*)dst)[i]);
        int2 s2 = __ldg(&((const int2*)src)[i]);
        g_adj[atomicAdd(&g_fill[d2.x], 1)] = s2.x;
        g_adj[atomicAdd(&g_fill[d2.y], 1)] = s2.y;
    }
    if (i == 0 && (E & 1)) {
        g_adj[atomicAdd(&g_fill[dst[E - 1]], 1)] = src[E - 1];
    }
}

// convert conv weights to fp16 once: g_w1h = [c1_wl; c1_wr], g_w2h = [c2_wl; c2_wr]
__global__ void wcvt_kernel(const float* __restrict__ w1l, const float* __restrict__ w1r,
                            const float* __restrict__ w2l, const float* __restrict__ w2r) {
    int i = blockIdx.x * blockDim.x + threadIdx.x;
    if (i < 4096) {
        int r = i >> 6, c = i & 63;
        g_w1h[i] = __float2half_rn(r < 32 ? w1l[r * 64 + c] : w1r[(r - 32) * 64 + c]);
    } else if (i < 4096 + 8192) {
        int j = i - 4096;
        int r = j >> 6, c = j & 63;
        g_w2h[j] = __float2half_rn(r < 64 ? w2l[r * 64 + c] : w2r[(r - 64) * 64 + c]);
    }
}

// h0 = relu(x @ pre_w + pre_b), fp16 only
__global__ void pre_kernel(const float* __restrict__ x,
                           const float* __restrict__ w,
                           const float* __restrict__ b, int N) {
    __shared__ float sw[5 * 32];
    __shared__ float sb[32];
    for (int i = threadIdx.x; i < 160; i += blockDim.x) sw[i] = w[i];
    if (threadIdx.x < 32) sb[threadIdx.x] = b[threadIdx.x];
    __syncthreads();
    int n = blockIdx.x * blockDim.x + threadIdx.x;
    if (n >= N) return;
    float xv[5];
#pragma unroll
    for (int k = 0; k < 5; k++) xv[k] = x[n * 5 + k];
    float o[32];
#pragma unroll
    for (int j = 0; j < 32; j++) {
        float acc = sb[j];
#pragma unroll
        for (int k = 0; k < 5; k++) acc = fmaf(xv[k], sw[k * 32 + j], acc);
        o[j] = fmaxf(acc, 0.f);
    }
#pragma unroll
    for (int j = 0; j < 16; j++)
        g_h0h[n * 16 + j] = __floats2half2_rn(o[2 * j], o[2 * j + 1]);
}

// ---------------------------------------------------------------------------
// conv1: root staged first, then gather mean(h0h) -> smem A [16 x 64] fp16
// (stride 72 halves), mma vs fp16 [Wl;Wr], l2norm+relu epilogue -> g_h1h.
__global__ __launch_bounds__(256, 4)
void conv1(const float* __restrict__ bl, int N) {
    extern __shared__ char dyn[];
    __half* wS = (__half*)dyn;                     // 64 x 72 halves = 9216 B
    float* sbias = (float*)(dyn + 9216);           // 256 B
    __half* sAall = (__half*)(dyn + 9472);         // 8 * 16*72*2 = 18432 B

    int tid = threadIdx.x;
    {
        uint4* wS4 = (uint4*)wS;                   // 9 uint4 per 72-half row
        const uint4* w4 = (const uint4*)g_w1h;     // 8 uint4 per 64-half row
        for (int i = tid; i < 512; i += 256) {
            int r = i >> 3, c8 = i & 7;
            wS4[r * 9 + c8] = w4[i];
        }
    }
    if (tid < 64) sbias[tid] = bl[tid];
    __syncthreads();

    int warp = tid >> 5, lane = tid & 31;
    int n0 = (blockIdx.x * 8 + warp) * 16;
    __half* sA = sAall + warp * (16 * 72);
    uint4* sA4 = (uint4*)sA;

    // root h0 (cols 32-63) first: issues under gather's latency shadow
#pragma unroll
    for (int p = 0; p < 2; p++) {
        int idx = p * 32 + lane;
        int node = idx >> 2, q = idx & 3;
        int n = n0 + node;
        uint4 v = make_uint4(0, 0, 0, 0);
        if (n < N) v = ((const uint4*)g_h0h)[n * 4 + q];
        sA4[node * 9 + 4 + q] = v;
    }

    // gather agg (cols 0-31): 4 lanes/node, 2 passes of 8 nodes
    {
        int sl = lane & 3;
#pragma unroll
        for (int p = 0; p < 2; p++) {
            int i = p * 8 + (lane >> 2);
            int n = n0 + i;
            float acc[8];
#pragma unroll
            for (int j = 0; j < 8; j++) acc[j] = 0.f;
            int deg = 0;
            if (n < N) {
                int start = g_rowptr[n];
                deg = g_deg[n];
                const uint4* h = (const uint4*)g_h0h;
                const int* adj = &g_adj[start];
                int k = 0;
                for (; k + 4 <= deg; k += 4) {
                    int s0 = __ldg(&adj[k + 0]);
                    int s1 = __ldg(&adj[k + 1]);
                    int s2 = __ldg(&adj[k + 2]);
                    int s3 = __ldg(&adj[k + 3]);
                    uint4 v0 = h[s0 * 4 + sl];
                    uint4 v1 = h[s1 * 4 + sl];
                    uint4 v2 = h[s2 * 4 + sl];
                    uint4 v3 = h[s3 * 4 + sl];
                    acc_u4(acc, v0); acc_u4(acc, v1); acc_u4(acc, v2); acc_u4(acc, v3);
                }
                if (k + 2 <= deg) {
                    int s0 = __ldg(&adj[k + 0]);
                    int s1 = __ldg(&adj[k + 1]);
                    uint4 v0 = h[s0 * 4 + sl];
                    uint4 v1 = h[s1 * 4 + sl];
                    acc_u4(acc, v0); acc_u4(acc, v1);
                    k += 2;
                }
                if (k < deg) {
                    uint4 v0 = h[__ldg(&adj[k]) * 4 + sl];
                    acc_u4(acc, v0);
                }
            }
            float inv = deg > 0 ? 1.f / (float)deg : 0.f;
            sA4[i * 9 + sl] = pack8h(acc, inv);
        }
    }
    __syncwarp();

    unsigned sAu = (unsigned)__cvta_generic_to_shared(sA);
    unsigned wSu = (unsigned)__cvta_generic_to_shared(wS);
    float c[8][4];
#pragma unroll
    for (int nt = 0; nt < 8; nt++) {
        float b0 = sbias[nt * 8 + (lane & 3) * 2];
        float b1 = sbias[nt * 8 + (lane & 3) * 2 + 1];
        c[nt][0] = b0; c[nt][1] = b1; c[nt][2] = b0; c[nt][3] = b1;
    }
#pragma unroll
    for (int ks = 0; ks < 4; ks++) {
        unsigned aaddr = sAu + ((lane & 15) * 72 + ks * 16 + ((lane >> 4) << 3)) * 2;
        unsigned a0, a1, a2, a3;
        LDSM_X4(a0, a1, a2, a3, aaddr);
#pragma unroll
        for (int np = 0; np < 4; np++) {
            unsigned baddr = wSu +
                ((ks * 16 + (lane & 7) + ((lane >> 3) & 1) * 8) * 72 +
                 np * 16 + (lane >> 4) * 8) * 2;
            unsigned b0, b1, b2, b3;
            LDSM_X4T(b0, b1, b2, b3, baddr);
            MMA16816(c[np * 2], a0, a1, a2, a3, b0, b1);
            MMA16816(c[np * 2 + 1], a0, a1, a2, a3, b2, b3);
        }
    }

    int q = lane >> 2;
    int nA = n0 + q, nB = nA + 8;
    float ssA = 0.f, ssB = 0.f;
#pragma unroll
    for (int nt = 0; nt < 8; nt++) {
        ssA += c[nt][0] * c[nt][0] + c[nt][1] * c[nt][1];
        ssB += c[nt][2] * c[nt][2] + c[nt][3] * c[nt][3];
    }
    ssA += __shfl_xor_sync(0xffffffffu, ssA, 1);
    ssA += __shfl_xor_sync(0xffffffffu, ssA, 2);
    ssB += __shfl_xor_sync(0xffffffffu, ssB, 1);
    ssB += __shfl_xor_sync(0xffffffffu, ssB, 2);
    float invA = 1.f / fmaxf(sqrtf(ssA), 1e-12f);
    float invB = 1.f / fmaxf(sqrtf(ssB), 1e-12f);
    if (nA < N) {
#pragma unroll
        for (int nt = 0; nt < 8; nt++)
            g_h1h[nA * 32 + nt * 4 + (lane & 3)] =
                __floats2half2_rn(fmaxf(c[nt][0] * invA, 0.f), fmaxf(c[nt][1] * invA, 0.f));
    }
    if (nB < N) {
#pragma unroll
        for (int nt = 0; nt < 8; nt++)
            g_h1h[nB * 32 + nt * 4 + (lane & 3)] =
                __floats2half2_rn(fmaxf(c[nt][2] * invB, 0.f), fmaxf(c[nt][3] * invB, 0.f));
    }
}

// ---------------------------------------------------------------------------
// conv2: root staged first, gather mean(h1h) -> smem A [16 x 128] fp16
// (stride 136), mma vs fp16 [Wl;Wr] (128x64), l2norm+relu+pool epilogue.
__global__ __launch_bounds__(256, 4)
void conv2(const int* __restrict__ batch, const float* __restrict__ bl, int N) {
    extern __shared__ char dyn[];
    __half* wS = (__half*)dyn;                     // 128 x 72 halves = 18432 B
    float* sbias = (float*)(dyn + 18432);          // 256 B
    __half* sAall = (__half*)(dyn + 18688);        // 8 * 16*136*2 = 34816 B

    int tid = threadIdx.x;
    {
        uint4* wS4 = (uint4*)wS;
        const uint4* w4 = (const uint4*)g_w2h;
        for (int i = tid; i < 1024; i += 256) {
            int r = i >> 3, c8 = i & 7;
            wS4[r * 9 + c8] = w4[i];
        }
    }
    if (tid < 64) sbias[tid] = bl[tid];
    __syncthreads();

    int warp = tid >> 5, lane = tid & 31;
    int n0 = (blockIdx.x * 8 + warp) * 16;
    __half* sA = sAall + warp * (16 * 136);
    uint4* sA4 = (uint4*)sA;

    // root h1 (cols 64-127) first
#pragma unroll
    for (int p = 0; p < 4; p++) {
        int idx = p * 32 + lane;
        int node = idx >> 3, q = idx & 7;
        int n = n0 + node;
        uint4 v = make_uint4(0, 0, 0, 0);
        if (n < N) v = ((const uint4*)g_h1h)[n * 8 + q];
        sA4[node * 17 + 8 + q] = v;
    }

    // gather agg (cols 0-63): 8 lanes/node, 4 passes of 4 nodes
    {
        int sl = lane & 7;
#pragma unroll
        for (int p = 0; p < 4; p++) {
            int i = p * 4 + (lane >> 3);
            int n = n0 + i;
            float acc[8];
#pragma unroll
            for (int j = 0; j < 8; j++) acc[j] = 0.f;
            int deg = 0;
            if (n < N) {
                int start = g_rowptr[n];
                deg = g_deg[n];
                const uint4* h = (const uint4*)g_h1h;
                const int* adj = &g_adj[start];
                int k = 0;
                for (; k + 4 <= deg; k += 4) {
                    int s0 = __ldg(&adj[k + 0]);
                    int s1 = __ldg(&adj[k + 1]);
                    int s2 = __ldg(&adj[k + 2]);
                    int s3 = __ldg(&adj[k + 3]);
                    uint4 v0 = h[s0 * 8 + sl];
                    uint4 v1 = h[s1 * 8 + sl];
                    uint4 v2 = h[s2 * 8 + sl];
                    uint4 v3 = h[s3 * 8 + sl];
                    acc_u4(acc, v0); acc_u4(acc, v1); acc_u4(acc, v2); acc_u4(acc, v3);
                }
                if (k + 2 <= deg) {
                    int s0 = __ldg(&adj[k + 0]);
                    int s1 = __ldg(&adj[k + 1]);
                    uint4 v0 = h[s0 * 8 + sl];
                    uint4 v1 = h[s1 * 8 + sl];
                    acc_u4(acc, v0); acc_u4(acc, v1);
                    k += 2;
                }
                if (k < deg) {
                    uint4 v0 = h[__ldg(&adj[k]) * 8 + sl];
                    acc_u4(acc, v0);
                }
            }
            float inv = deg > 0 ? 1.f / (float)deg : 0.f;
            sA4[i * 17 + sl] = pack8h(acc, inv);
        }
    }
    __syncwarp();

    unsigned sAu = (unsigned)__cvta_generic_to_shared(sA);
    unsigned wSu = (unsigned)__cvta_generic_to_shared(wS);
    float c[8][4];
#pragma unroll
    for (int nt = 0; nt < 8; nt++) {
        float b0 = sbias[nt * 8 + (lane & 3) * 2];
        float b1 = sbias[nt * 8 + (lane & 3) * 2 + 1];
        c[nt][0] = b0; c[nt][1] = b1; c[nt][2] = b0; c[nt][3] = b1;
    }
#pragma unroll
    for (int ks = 0; ks < 8; ks++) {
        unsigned aaddr = sAu + ((lane & 15) * 136 + ks * 16 + ((lane >> 4) << 3)) * 2;
        unsigned a0, a1, a2, a3;
        LDSM_X4(a0, a1, a2, a3, aaddr);
#pragma unroll
        for (int np = 0; np < 4; np++) {
            unsigned baddr = wSu +
                ((ks * 16 + (lane & 7) + ((lane >> 3) & 1) * 8) * 72 +
                 np * 16 + (lane >> 4) * 8) * 2;
            unsigned b0, b1, b2, b3;
            LDSM_X4T(b0, b1, b2, b3, baddr);
            MMA16816(c[np * 2], a0, a1, a2, a3, b0, b1);
            MMA16816(c[np * 2 + 1], a0, a1, a2, a3, b2, b3);
        }
    }

    int q = lane >> 2;
    int nA = n0 + q, nB = nA + 8;
    float ssA = 0.f, ssB = 0.f;
#pragma unroll
    for (int nt = 0; nt < 8; nt++) {
        ssA += c[nt][0] * c[nt][0] + c[nt][1] * c[nt][1];
        ssB += c[nt][2] * c[nt][2] + c[nt][3] * c[nt][3];
    }
    ssA += __shfl_xor_sync(0xffffffffu, ssA, 1);
    ssA += __shfl_xor_sync(0xffffffffu, ssA, 2);
    ssB += __shfl_xor_sync(0xffffffffu, ssB, 1);
    ssB += __shfl_xor_sync(0xffffffffu, ssB, 2);
    float invA = 1.f / fmaxf(sqrtf(ssA), 1e-12f);
    float invB = 1.f / fmaxf(sqrtf(ssB), 1e-12f);
    if (nA < N) {
        int b = batch[nA];
        int cb = (lane & 3) * 2;
#pragma unroll
        for (int nt = 0; nt < 8; nt++) {
            red_add_f32(&g_gsum[b * 64 + nt * 8 + cb], fmaxf(c[nt][0] * invA, 0.f));
            red_add_f32(&g_gsum[b * 64 + nt * 8 + cb + 1], fmaxf(c[nt][1] * invA, 0.f));
        }
        if ((lane & 3) == 0) red_add_f32(&g_gcnt[b], 1.f);
    }
    if (nB < N) {
        int b = batch[nB];
        int cb = (lane & 3) * 2;
#pragma unroll
        for (int nt = 0; nt < 8; nt++) {
            red_add_f32(&g_gsum[b * 64 + nt * 8 + cb], fmaxf(c[nt][2] * invB, 0.f));
            red_add_f32(&g_gsum[b * 64 + nt * 8 + cb + 1], fmaxf(c[nt][3] * invB, 0.f));
        }
        if ((lane & 3) == 0) red_add_f32(&g_gcnt[b], 1.f);
    }
}

// head MLP
__global__ void head_kernel(const float* __restrict__ p1w, const float* __restrict__ p1b,
                            const float* __restrict__ p2w, const float* __restrict__ p2b,
                            const float* __restrict__ ow, const float* __restrict__ ob,
                            float* __restrict__ out) {
    int g = blockIdx.x;
    int t = threadIdx.x;
    __shared__ float sg[64];
    __shared__ float sh[64];
    __shared__ float s2[16];

    float c = g_gcnt[g];
    float invc = 1.f / fmaxf(c, 1.f);
    sg[t] = g_gsum[g * 64 + t] * invc;
    __syncthreads();

    float acc = p1b[t];
#pragma unroll 8
    for (int k = 0; k < 64; k++) acc = fmaf(sg[k], p1w[k * 64 + t], acc);
    sh[t] = fmaxf(acc, 0.f);
    __syncthreads();

    if (t < 16) {
        float a = p2b[t];
#pragma unroll 8
        for (int k = 0; k < 64; k++) a = fmaf(sh[k], p2w[k * 16 + t], a);
        s2[t] = fmaxf(a, 0.f);
    }
    __syncthreads();

    if (t == 0) {
        float a = ob[0];
#pragma unroll
        for (int k = 0; k < 16; k++) a = fmaf(s2[k], ow[k], a);
        out[g] = a;
    }
}

// ---------------------------------------------------------------------------
extern "C" void kernel_launch(void* const* d_in, const int* in_sizes, int n_in,
                              void* d_out, int out_size) {
    const float* x = (const float*)d_in[0];
    const int* ei = (const int*)d_in[1];
    const int* batch = (const int*)d_in[2];

    int base = n_in - 14;
    const float* pre_w = (const float*)d_in[base + 0];
    const float* pre_b = (const float*)d_in[base + 1];
    const float* c1_wl = (const float*)d_in[base + 2];
    const float* c1_bl = (const float*)d_in[base + 3];
    const float* c1_wr = (const float*)d_in[base + 4];
    const float* c2_wl = (const float*)d_in[base + 5];
    const float* c2_bl = (const float*)d_in[base + 6];
    const float* c2_wr = (const float*)d_in[base + 7];
    const float* p1_w = (const float*)d_in[base + 8];
    const float* p1_b = (const float*)d_in[base + 9];
    const float* p2_w = (const float*)d_in[base + 10];
    const float* p2_b = (const float*)d_in[base + 11];
    const float* o_w = (const float*)d_in[base + 12];
    const float* o_b = (const float*)d_in[base + 13];

    int N = in_sizes[0] / 5;
    int E = in_sizes[1] / 2;
    const int* src = ei;
    const int* dst = ei + E;
    float* out = (float*)d_out;

    const int smem1 = 9216 + 256 + 18432;     // 27904 B
    const int smem2 = 18432 + 256 + 34816;    // 53504 B
    cudaFuncSetAttribute(conv1, cudaFuncAttributeMaxDynamicSharedMemorySize, smem1);
    cudaFuncSetAttribute(conv2, cudaFuncAttributeMaxDynamicSharedMemorySize, smem2);

    int nb = (N + SCAN_B - 1) / SCAN_B;
    int nodeblk = (N + 127) / 128;

    zero_small<<<256, 256>>>(N);                               // 0
    hist_kernel<<<(E + 255) / 256, 256>>>(dst, E);             // 1
    scan_kernel<<<nb, SCAN_B>>>(N);                            // 2
    place_kernel<<<(E / 2 + 255) / 256, 256>>>(src, dst, E);   // 3 (profiled)
    wcvt_kernel<<<48, 256>>>(c1_wl, c1_wr, c2_wl, c2_wr);      // 4
    pre_kernel<<<(N + 255) / 256, 256>>>(x, pre_w, pre_b, N);  // 5

    conv1<<<nodeblk, 256, smem1>>>(c1_bl, N);                  // 6
    conv2<<<nodeblk, 256, smem2>>>(batch, c2_bl, N);           // 7

    head_kernel<<<out_size, 64>>>(p1_w, p1_b, p2_w, p2_b, o_w, o_b, out); // 8
}

// round 17
// speedup vs baseline: 1.0433x; 1.0433x over previous
#include <cuda_runtime.h>
#include <cuda_fp16.h>
#include <math.h>

// ---------------------------------------------------------------------------
// GNN_11957188952096: pre-linear -> SAGE(32->64) -> SAGE(64->64) -> pool -> MLP
// N=100000 nodes, E=1600000 edges, G=512 graphs
// CSR gather (fp16) + tensor-core (mma.sync) combine fused per conv.
// State cleanup at end of each launch (globals zero-initialized at load).
// ---------------------------------------------------------------------------

#define MAXN 100000
#define MAXE 1600000
#define MAXG 512
#define SCAN_B 1024
#define AFLAG (1u << 30)
#define PFLAG (2u << 30)

__device__ __half2 g_h0h[MAXN * 16];   // pre-linear output (fp16), 32 feats
__device__ __half2 g_h1h[MAXN * 32];   // conv1 output (fp16), 64 feats
__device__ __align__(16) __half g_w1h[64 * 64];    // [c1_wl; c1_wr] fp16
__device__ __align__(16) __half g_w2h[128 * 64];   // [c2_wl; c2_wr] fp16
__device__ float g_gsum[MAXG * 64];    // zero-init at load; re-zeroed by head
__device__ float g_gcnt[MAXG];         // zero-init at load; re-zeroed by head
__device__ int g_deg[MAXN];            // zero-init at load; re-zeroed by head
__device__ int g_rowptr[MAXN];
__device__ int g_fill[MAXN];
__device__ int g_adj[MAXE];
__device__ unsigned g_state[128];      // zero-init at load; re-zeroed by head

__device__ __forceinline__ void red_add_f32(float* addr, float v) {
    asm volatile("red.global.add.f32 [%0], %1;" :: "l"(addr), "f"(v) : "memory");
}
__device__ __forceinline__ void red_add_s32(int* addr, int v) {
    asm volatile("red.global.add.s32 [%0], %1;" :: "l"(addr), "r"(v) : "memory");
}
__device__ __forceinline__ void acc_u4(float* acc, uint4 v) {
    float2 f;
    f = __half22float2(*(__half2*)&v.x);            acc[0] += f.x; acc[1] += f.y;
    f = __half22float2(*(((__half2*)&v.x) + 1));    acc[2] += f.x; acc[3] += f.y;
    f = __half22float2(*(__half2*)&v.z);            acc[4] += f.x; acc[5] += f.y;
    f = __half22float2(*(((__half2*)&v.z) + 1));    acc[6] += f.x; acc[7] += f.y;
}
__device__ __forceinline__ uint4 pack8h(const float* a, float s) {
    uint4 o;
    *(__half2*)&o.x = __floats2half2_rn(a[0] * s, a[1] * s);
    *(((__half2*)&o.x) + 1) = __floats2half2_rn(a[2] * s, a[3] * s);
    *(__half2*)&o.z = __floats2half2_rn(a[4] * s, a[5] * s);
    *(((__half2*)&o.z) + 1) = __floats2half2_rn(a[6] * s, a[7] * s);
    return o;
}

#define LDSM_X4(r0, r1, r2, r3, a) \
    asm volatile("ldmatrix.sync.aligned.m8n8.x4.shared.b16 {%0,%1,%2,%3},[%4];" \
                 : "=r"(r0), "=r"(r1), "=r"(r2), "=r"(r3) : "r"(a))
#define LDSM_X4T(r0, r1, r2, r3, a) \
    asm volatile("ldmatrix.sync.aligned.m8n8.x4.trans.shared.b16 {%0,%1,%2,%3},[%4];" \
                 : "=r"(r0), "=r"(r1), "=r"(r2), "=r"(r3) : "r"(a))
#define MMA16816(c, a0, a1, a2, a3, b0, b1) \
    asm volatile("mma.sync.aligned.m16n8k16.row.col.f32.f16.f16.f32 " \
                 "{%0,%1,%2,%3},{%4,%5,%6,%7},{%8,%9},{%0,%1,%2,%3};" \
                 : "+f"(c[0]), "+f"(c[1]), "+f"(c[2]), "+f"(c[3]) \
                 : "r"(a0), "r"(a1), "r"(a2), "r"(a3), "r"(b0), "r"(b1))

// ---------------------------------------------------------------------------
// fused: pre-linear (FMA-bound) + weight convert + degree histogram
// (atomic-latency-bound) co-resident in one launch.
__global__ __launch_bounds__(256)
void fused_pre_hist(const float* __restrict__ x,
                    const float* __restrict__ w, const float* __restrict__ b,
                    const float* __restrict__ w1l, const float* __restrict__ w1r,
                    const float* __restrict__ w2l, const float* __restrict__ w2r,
                    const int* __restrict__ dst, int N, int E) {
    __shared__ float sw[5 * 32];
    __shared__ float sb[32];
    for (int i = threadIdx.x; i < 160; i += blockDim.x) sw[i] = w[i];
    if (threadIdx.x < 32) sb[threadIdx.x] = b[threadIdx.x];
    __syncthreads();

    int gi = blockIdx.x * blockDim.x + threadIdx.x;
    int gsz = gridDim.x * blockDim.x;

    // weight convert (12288 elems)
    if (gi < 4096) {
        int r = gi >> 6, c = gi & 63;
        g_w1h[gi] = __float2half_rn(r < 32 ? w1l[r * 64 + c] : w1r[(r - 32) * 64 + c]);
    } else if (gi < 12288) {
        int j = gi - 4096;
        int r = j >> 6, c = j & 63;
        g_w2h[j] = __float2half_rn(r < 64 ? w2l[r * 64 + c] : w2r[(r - 64) * 64 + c]);
    }

    // pre-linear: h0 = relu(x @ pre_w + pre_b) -> fp16
    if (gi < N) {
        int n = gi;
        float xv[5];
#pragma unroll
        for (int k = 0; k < 5; k++) xv[k] = x[n * 5 + k];
        float o[32];
#pragma unroll
        for (int j = 0; j < 32; j++) {
            float acc = sb[j];
#pragma unroll
            for (int k = 0; k < 5; k++) acc = fmaf(xv[k], sw[k * 32 + j], acc);
            o[j] = fmaxf(acc, 0.f);
        }
#pragma unroll
        for (int j = 0; j < 16; j++)
            g_h0h[n * 16 + j] = __floats2half2_rn(o[2 * j], o[2 * j + 1]);
    }

    // degree histogram (grid-stride; fire-and-forget REDs)
    for (int e = gi; e < E; e += gsz) red_add_s32(&g_deg[__ldg(&dst[e])], 1);
}

// exclusive scan via decoupled lookback; also fill = rowptr
__global__ void scan_kernel(int N) {
    __shared__ int buf0[SCAN_B], buf1[SCAN_B];
    __shared__ int s_run;
    int t = threadIdx.x, bid = blockIdx.x;
    int g = bid * SCAN_B + t;
    int v = (g < N) ? g_deg[g] : 0;
    buf0[t] = v;
    int* a = buf0; int* b = buf1;
#pragma unroll
    for (int off = 1; off < SCAN_B; off <<= 1) {
        __syncthreads();
        b[t] = (t >= off) ? a[t] + a[t - off] : a[t];
        int* tmp = a; a = b; b = tmp;
    }
    __syncthreads();
    int incl = a[t];
    int bsum = a[SCAN_B - 1];
    if (t == 0) {
        if (bid == 0) {
            atomicExch(&g_state[0], PFLAG | (unsigned)bsum);
            s_run = 0;
        } else {
            atomicExch(&g_state[bid], AFLAG | (unsigned)bsum);
            int run = 0;
            for (int j = bid - 1; j >= 0; j--) {
                unsigned s;
                do { s = atomicAdd(&g_state[j], 0u); } while ((s >> 30) == 0);
                run += (int)(s & 0x3FFFFFFFu);
                if (s & PFLAG) break;
            }
            atomicExch(&g_state[bid], PFLAG | (unsigned)(run + bsum));
            s_run = run;
        }
    }
    __syncthreads();
    if (g < N) {
        int r = incl - v + s_run;
        g_rowptr[g] = r;
        g_fill[g] = r;
    }
}

// placement: fill pre-initialized to rowptr -> single atomic per edge (2/thread)
__global__ void place_kernel(const int* __restrict__ src, const int* __restrict__ dst,
                             int E) {
    int i = blockIdx.x * blockDim.x + threadIdx.x;
    int E2 = E >> 1;
    if (i < E2) {
        int2 d2 = __ldg(&((const int2*)dst)[i]);
        int2 s2 = __ldg(&((const int2*)src)[i]);
        g_adj[atomicAdd(&g_fill[d2.x], 1)] = s2.x;
        g_adj[atomicAdd(&g_fill[d2.y], 1)] = s2.y;
    }
    if (i == 0 && (E & 1)) {
        g_adj[atomicAdd(&g_fill[dst[E - 1]], 1)] = src[E - 1];
    }
}

// ---------------------------------------------------------------------------
// conv1: root staged first, then gather mean(h0h) -> smem A [16 x 64] fp16
// (stride 72 halves), mma vs fp16 [Wl;Wr], l2norm+relu epilogue -> g_h1h.
__global__ __launch_bounds__(256, 4)
void conv1(const float* __restrict__ bl, int N) {
    extern __shared__ char dyn[];
    __half* wS = (__half*)dyn;                     // 64 x 72 halves = 9216 B
    float* sbias = (float*)(dyn + 9216);           // 256 B
    __half* sAall = (__half*)(dyn + 9472);         // 8 * 16*72*2 = 18432 B

    int tid = threadIdx.x;
    {
        uint4* wS4 = (uint4*)wS;
        const uint4* w4 = (const uint4*)g_w1h;
        for (int i = tid; i < 512; i += 256) {
            int r = i >> 3, c8 = i & 7;
            wS4[r * 9 + c8] = w4[i];
        }
    }
    if (tid < 64) sbias[tid] = bl[tid];
    __syncthreads();

    int warp = tid >> 5, lane = tid & 31;
    int n0 = (blockIdx.x * 8 + warp) * 16;
    __half* sA = sAall + warp * (16 * 72);
    uint4* sA4 = (uint4*)sA;

    // root h0 (cols 32-63) first
#pragma unroll
    for (int p = 0; p < 2; p++) {
        int idx = p * 32 + lane;
        int node = idx >> 2, q = idx & 3;
        int n = n0 + node;
        uint4 v = make_uint4(0, 0, 0, 0);
        if (n < N) v = ((const uint4*)g_h0h)[n * 4 + q];
        sA4[node * 9 + 4 + q] = v;
    }

    // gather agg (cols 0-31): 4 lanes/node, 2 passes of 8 nodes
    {
        int sl = lane & 3;
#pragma unroll
        for (int p = 0; p < 2; p++) {
            int i = p * 8 + (lane >> 2);
            int n = n0 + i;
            float acc[8];
#pragma unroll
            for (int j = 0; j < 8; j++) acc[j] = 0.f;
            int deg = 0;
            if (n < N) {
                int start = g_rowptr[n];
                deg = g_deg[n];
                const uint4* h = (const uint4*)g_h0h;
                const int* adj = &g_adj[start];
                int k = 0;
                for (; k + 4 <= deg; k += 4) {
                    int s0 = __ldg(&adj[k + 0]);
                    int s1 = __ldg(&adj[k + 1]);
                    int s2 = __ldg(&adj[k + 2]);
                    int s3 = __ldg(&adj[k + 3]);
                    uint4 v0 = h[s0 * 4 + sl];
                    uint4 v1 = h[s1 * 4 + sl];
                    uint4 v2 = h[s2 * 4 + sl];
                    uint4 v3 = h[s3 * 4 + sl];
                    acc_u4(acc, v0); acc_u4(acc, v1); acc_u4(acc, v2); acc_u4(acc, v3);
                }
                if (k + 2 <= deg) {
                    int s0 = __ldg(&adj[k + 0]);
                    int s1 = __ldg(&adj[k + 1]);
                    uint4 v0 = h[s0 * 4 + sl];
                    uint4 v1 = h[s1 * 4 + sl];
                    acc_u4(acc, v0); acc_u4(acc, v1);
                    k += 2;
                }
                if (k < deg) {
                    uint4 v0 = h[__ldg(&adj[k]) * 4 + sl];
                    acc_u4(acc, v0);
                }
            }
            float inv = deg > 0 ? 1.f / (float)deg : 0.f;
            sA4[i * 9 + sl] = pack8h(acc, inv);
        }
    }
    __syncwarp();

    unsigned sAu = (unsigned)__cvta_generic_to_shared(sA);
    unsigned wSu = (unsigned)__cvta_generic_to_shared(wS);
    float c[8][4];
#pragma unroll
    for (int nt = 0; nt < 8; nt++) {
        float b0 = sbias[nt * 8 + (lane & 3) * 2];
        float b1 = sbias[nt * 8 + (lane & 3) * 2 + 1];
        c[nt][0] = b0; c[nt][1] = b1; c[nt][2] = b0; c[nt][3] = b1;
    }
#pragma unroll
    for (int ks = 0; ks < 4; ks++) {
        unsigned aaddr = sAu + ((lane & 15) * 72 + ks * 16 + ((lane >> 4) << 3)) * 2;
        unsigned a0, a1, a2, a3;
        LDSM_X4(a0, a1, a2, a3, aaddr);
#pragma unroll
        for (int np = 0; np < 4; np++) {
            unsigned baddr = wSu +
                ((ks * 16 + (lane & 7) + ((lane >> 3) & 1) * 8) * 72 +
                 np * 16 + (lane >> 4) * 8) * 2;
            unsigned b0, b1, b2, b3;
            LDSM_X4T(b0, b1, b2, b3, baddr);
            MMA16816(c[np * 2], a0, a1, a2, a3, b0, b1);
            MMA16816(c[np * 2 + 1], a0, a1, a2, a3, b2, b3);
        }
    }

    int q = lane >> 2;
    int nA = n0 + q, nB = nA + 8;
    float ssA = 0.f, ssB = 0.f;
#pragma unroll
    for (int nt = 0; nt < 8; nt++) {
        ssA += c[nt][0] * c[nt][0] + c[nt][1] * c[nt][1];
        ssB += c[nt][2] * c[nt][2] + c[nt][3] * c[nt][3];
    }
    ssA += __shfl_xor_sync(0xffffffffu, ssA, 1);
    ssA += __shfl_xor_sync(0xffffffffu, ssA, 2);
    ssB += __shfl_xor_sync(0xffffffffu, ssB, 1);
    ssB += __shfl_xor_sync(0xffffffffu, ssB, 2);
    float invA = 1.f / fmaxf(sqrtf(ssA), 1e-12f);
    float invB = 1.f / fmaxf(sqrtf(ssB), 1e-12f);
    if (nA < N) {
#pragma unroll
        for (int nt = 0; nt < 8; nt++)
            g_h1h[nA * 32 + nt * 4 + (lane & 3)] =
                __floats2half2_rn(fmaxf(c[nt][0] * invA, 0.f), fmaxf(c[nt][1] * invA, 0.f));
    }
    if (nB < N) {
#pragma unroll
        for (int nt = 0; nt < 8; nt++)
            g_h1h[nB * 32 + nt * 4 + (lane & 3)] =
                __floats2half2_rn(fmaxf(c[nt][2] * invB, 0.f), fmaxf(c[nt][3] * invB, 0.f));
    }
}

// ---------------------------------------------------------------------------
// conv2: root staged first, gather mean(h1h) -> smem A [16 x 128] fp16
// (stride 136), mma vs fp16 [Wl;Wr] (128x64), l2norm+relu+pool epilogue.
__global__ __launch_bounds__(256, 4)
void conv2(const int* __restrict__ batch, const float* __restrict__ bl, int N) {
    extern __shared__ char dyn[];
    __half* wS = (__half*)dyn;                     // 128 x 72 halves = 18432 B
    float* sbias = (float*)(dyn + 18432);          // 256 B
    __half* sAall = (__half*)(dyn + 18688);        // 8 * 16*136*2 = 34816 B

    int tid = threadIdx.x;
    {
        uint4* wS4 = (uint4*)wS;
        const uint4* w4 = (const uint4*)g_w2h;
        for (int i = tid; i < 1024; i += 256) {
            int r = i >> 3, c8 = i & 7;
            wS4[r * 9 + c8] = w4[i];
        }
    }
    if (tid < 64) sbias[tid] = bl[tid];
    __syncthreads();

    int warp = tid >> 5, lane = tid & 31;
    int n0 = (blockIdx.x * 8 + warp) * 16;
    __half* sA = sAall + warp * (16 * 136);
    uint4* sA4 = (uint4*)sA;

    // root h1 (cols 64-127) first
#pragma unroll
    for (int p = 0; p < 4; p++) {
        int idx = p * 32 + lane;
        int node = idx >> 3, q = idx & 7;
        int n = n0 + node;
        uint4 v = make_uint4(0, 0, 0, 0);
        if (n < N) v = ((const uint4*)g_h1h)[n * 8 + q];
        sA4[node * 17 + 8 + q] = v;
    }

    // gather agg (cols 0-63): 8 lanes/node, 4 passes of 4 nodes
    {
        int sl = lane & 7;
#pragma unroll
        for (int p = 0; p < 4; p++) {
            int i = p * 4 + (lane >> 3);
            int n = n0 + i;
            float acc[8];
#pragma unroll
            for (int j = 0; j < 8; j++) acc[j] = 0.f;
            int deg = 0;
            if (n < N) {
                int start = g_rowptr[n];
                deg = g_deg[n];
                const uint4* h = (const uint4*)g_h1h;
                const int* adj = &g_adj[start];
                int k = 0;
                for (; k + 4 <= deg; k += 4) {
                    int s0 = __ldg(&adj[k + 0]);
                    int s1 = __ldg(&adj[k + 1]);
                    int s2 = __ldg(&adj[k + 2]);
                    int s3 = __ldg(&adj[k + 3]);
                    uint4 v0 = h[s0 * 8 + sl];
                    uint4 v1 = h[s1 * 8 + sl];
                    uint4 v2 = h[s2 * 8 + sl];
                    uint4 v3 = h[s3 * 8 + sl];
                    acc_u4(acc, v0); acc_u4(acc, v1); acc_u4(acc, v2); acc_u4(acc, v3);
                }
                if (k + 2 <= deg) {
                    int s0 = __ldg(&adj[k + 0]);
                    int s1 = __ldg(&adj[k + 1]);
                    uint4 v0 = h[s0 * 8 + sl];
                    uint4 v1 = h[s1 * 8 + sl];
                    acc_u4(acc, v0); acc_u4(acc, v1);
                    k += 2;
                }
                if (k < deg) {
                    uint4 v0 = h[__ldg(&adj[k]) * 8 + sl];
                    acc_u4(acc, v0);
                }
            }
            float inv = deg > 0 ? 1.f / (float)deg : 0.f;
            sA4[i * 17 + sl] = pack8h(acc, inv);
        }
    }
    __syncwarp();

    unsigned sAu = (unsigned)__cvta_generic_to_shared(sA);
    unsigned wSu = (unsigned)__cvta_generic_to_shared(wS);
    float c[8][4];
#pragma unroll
    for (int nt = 0; nt < 8; nt++) {
        float b0 = sbias[nt * 8 + (lane & 3) * 2];
        float b1 = sbias[nt * 8 + (lane & 3) * 2 + 1];
        c[nt][0] = b0; c[nt][1] = b1; c[nt][2] = b0; c[nt][3] = b1;
    }
#pragma unroll
    for (int ks = 0; ks < 8; ks++) {
        unsigned aaddr = sAu + ((lane & 15) * 136 + ks * 16 + ((lane >> 4) << 3)) * 2;
        unsigned a0, a1, a2, a3;
        LDSM_X4(a0, a1, a2, a3, aaddr);
#pragma unroll
        for (int np = 0; np < 4; np++) {
            unsigned baddr = wSu +
                ((ks * 16 + (lane & 7) + ((lane >> 3) & 1) * 8) * 72 +
                 np * 16 + (lane >> 4) * 8) * 2;
            unsigned b0, b1, b2, b3;
            LDSM_X4T(b0, b1, b2, b3, baddr);
            MMA16816(c[np * 2], a0, a1, a2, a3, b0, b1);
            MMA16816(c[np * 2 + 1], a0, a1, a2, a3, b2, b3);
        }
    }

    int q = lane >> 2;
    int nA = n0 + q, nB = nA + 8;
    float ssA = 0.f, ssB = 0.f;
#pragma unroll
    for (int nt = 0; nt < 8; nt++) {
        ssA += c[nt][0] * c[nt][0] + c[nt][1] * c[nt][1];
        ssB += c[nt][2] * c[nt][2] + c[nt][3] * c[nt][3];
    }
    ssA += __shfl_xor_sync(0xffffffffu, ssA, 1);
    ssA += __shfl_xor_sync(0xffffffffu, ssA, 2);
    ssB += __shfl_xor_sync(0xffffffffu, ssB, 1);
    ssB += __shfl_xor_sync(0xffffffffu, ssB, 2);
    float invA = 1.f / fmaxf(sqrtf(ssA), 1e-12f);
    float invB = 1.f / fmaxf(sqrtf(ssB), 1e-12f);
    if (nA < N) {
        int b = batch[nA];
        int cb = (lane & 3) * 2;
#pragma unroll
        for (int nt = 0; nt < 8; nt++) {
            red_add_f32(&g_gsum[b * 64 + nt * 8 + cb], fmaxf(c[nt][0] * invA, 0.f));
            red_add_f32(&g_gsum[b * 64 + nt * 8 + cb + 1], fmaxf(c[nt][1] * invA, 0.f));
        }
        if ((lane & 3) == 0) red_add_f32(&g_gcnt[b], 1.f);
    }
    if (nB < N) {
        int b = batch[nB];
        int cb = (lane & 3) * 2;
#pragma unroll
        for (int nt = 0; nt < 8; nt++) {
            red_add_f32(&g_gsum[b * 64 + nt * 8 + cb], fmaxf(c[nt][2] * invB, 0.f));
            red_add_f32(&g_gsum[b * 64 + nt * 8 + cb + 1], fmaxf(c[nt][3] * invB, 0.f));
        }
        if ((lane & 3) == 0) red_add_f32(&g_gcnt[b], 1.f);
    }
}

// head MLP + end-of-launch state cleanup (next launch / re-validation safe)
__global__ void head_kernel(const float* __restrict__ p1w, const float* __restrict__ p1b,
                            const float* __restrict__ p2w, const float* __restrict__ p2b,
                            const float* __restrict__ ow, const float* __restrict__ ob,
                            float* __restrict__ out, int N) {
    int g = blockIdx.x;
    int t = threadIdx.x;
    __shared__ float sg[64];
    __shared__ float sh[64];
    __shared__ float s2[16];

    float c = g_gcnt[g];
    float invc = 1.f / fmaxf(c, 1.f);
    sg[t] = g_gsum[g * 64 + t] * invc;
    __syncthreads();

    // this block's pooled inputs are consumed; re-zero OWN slice only
    g_gsum[g * 64 + t] = 0.f;
    if (t == 0) g_gcnt[g] = 0.f;

    float acc = p1b[t];
#pragma unroll 8
    for (int k = 0; k < 64; k++) acc = fmaf(sg[k], p1w[k * 64 + t], acc);
    sh[t] = fmaxf(acc, 0.f);
    __syncthreads();

    if (t < 16) {
        float a = p2b[t];
#pragma unroll 8
        for (int k = 0; k < 64; k++) a = fmaf(sh[k], p2w[k * 16 + t], a);
        s2[t] = fmaxf(a, 0.f);
    }
    __syncthreads();

    if (t == 0) {
        float a = ob[0];
#pragma unroll
        for (int k = 0; k < 16; k++) a = fmaf(s2[k], ow[k], a);
        out[g] = a;
    }

    // cleanup of state not read by head: deg + scan state
    int gi = g * 64 + t;
    int gsz = gridDim.x * 64;
    for (int k = gi; k < N; k += gsz) g_deg[k] = 0;
    if (gi < 128) g_state[gi] = 0u;
}

// ---------------------------------------------------------------------------
extern "C" void kernel_launch(void* const* d_in, const int* in_sizes, int n_in,
                              void* d_out, int out_size) {
    const float* x = (const float*)d_in[0];
    const int* ei = (const int*)d_in[1];
    const int* batch = (const int*)d_in[2];

    int base = n_in - 14;
    const float* pre_w = (const float*)d_in[base + 0];
    const float* pre_b = (const float*)d_in[base + 1];
    const float* c1_wl = (const float*)d_in[base + 2];
    const float* c1_bl = (const float*)d_in[base + 3];
    const float* c1_wr = (const float*)d_in[base + 4];
    const float* c2_wl = (const float*)d_in[base + 5];
    const float* c2_bl = (const float*)d_in[base + 6];
    const float* c2_wr = (const float*)d_in[base + 7];
    const float* p1_w = (const float*)d_in[base + 8];
    const float* p1_b = (const float*)d_in[base + 9];
    const float* p2_w = (const float*)d_in[base + 10];
    const float* p2_b = (const float*)d_in[base + 11];
    const float* o_w = (const float*)d_in[base + 12];
    const float* o_b = (const float*)d_in[base + 13];

    int N = in_sizes[0] / 5;
    int E = in_sizes[1] / 2;
    const int* src = ei;
    const int* dst = ei + E;
    float* out = (float*)d_out;

    const int smem1 = 9216 + 256 + 18432;     // 27904 B
    const int smem2 = 18432 + 256 + 34816;    // 53504 B
    cudaFuncSetAttribute(conv1, cudaFuncAttributeMaxDynamicSharedMemorySize, smem1);
    cudaFuncSetAttribute(conv2, cudaFuncAttributeMaxDynamicSharedMemorySize, smem2);

    int nb = (N + SCAN_B - 1) / SCAN_B;
    int nodeblk = (N + 127) / 128;

    fused_pre_hist<<<1024, 256>>>(x, pre_w, pre_b, c1_wl, c1_wr, c2_wl, c2_wr,
                                  dst, N, E);                  // 0
    scan_kernel<<<nb, SCAN_B>>>(N);                            // 1
    place_kernel<<<(E / 2 + 255) / 256, 256>>>(src, dst, E);   // 2
    conv1<<<nodeblk, 256, smem1>>>(c1_bl, N);                  // 3 (profiled)
    conv2<<<nodeblk, 256, smem2>>>(batch, c2_bl, N);           // 4
    head_kernel<<<out_size, 64>>>(p1_w, p1_b, p2_w, p2_b, o_w, o_b, out, N); // 5
}